// round 4
// baseline (speedup 1.0000x reference)
#include <cuda_runtime.h>
#include <math.h>

// Problem constants
#define B_    16
#define CIN   384
#define L0    65536   // B * 64*64
#define L1    16384   // B * 32*32
#define N0_   4096
#define N1_   1024
#define CDIM_ 128
#define KK_   64
#define BK    16

// weight buffer layout per scale: w1[1152*384] | w2f[128*512] | w2s[64*512]
#define W1SZ  (1152 * CIN)
#define W2FSZ (128 * 512)
#define W2SSZ (64 * 512)
#define WSTRIDE (W1SZ + W2FSZ + W2SSZ)

// -------- scratch (device globals; no allocation allowed) --------
__device__ float g_xt  [CIN * L0];        // x transposed, tf32-rounded [C, B*N0]
__device__ float g_x1t [CIN * L1];        // pooled x, tf32-rounded [C, B*N1]
__device__ float g_hidden[1152 * L0];     // relu(hidden), tf32-rounded
__device__ float g_feat[CDIM_ * L0];      // local_feat fp32 [128, L]
__device__ float g_Z   [65 * L0];         // E = exp(scores|dustbin) [65, L]
__device__ float g_out [2 * B_ * CDIM_ * KK_];
__device__ float g_wbuf[2 * WSTRIDE];     // tf32-rounded weights per scale
__device__ float g_bbuf[2 * 1152];        // layer-1 biases per scale
__device__ float g_c   [B_ * N0_];        // sinkhorn column scaling c_n

__device__ __forceinline__ float* bufptr(int id) {
    switch (id) {
        case 0: return g_xt;
        case 1: return g_x1t;
        case 2: return g_hidden;
        case 3: return g_feat;
        case 4: return g_Z;
        case 5: return g_wbuf;
        default: return g_bbuf;
    }
}

__device__ __forceinline__ float tf32r(float x) {
    unsigned u;
    asm("cvt.rna.tf32.f32 %0, %1;\n" : "=r"(u) : "f"(x));
    return __uint_as_float(u);
}

// -------- layout transforms (store tf32-rounded) --------
__global__ void transpose_k(const float* __restrict__ x) {
    int idx = blockIdx.x * 256 + threadIdx.x;
    int c = idx >> 16;
    int l = idx & 65535;
    int b = l >> 12;
    int n = l & 4095;
    g_xt[idx] = tf32r(x[((long)(b * CIN + c) << 12) + n]);
}

__global__ void pool_k(const float* __restrict__ x) {
    int idx = blockIdx.x * 256 + threadIdx.x;
    int c = idx >> 14;
    int l = idx & 16383;
    int b = l >> 10;
    int p = l & 1023;
    int i = p >> 5, j = p & 31;
    const float* xb = x + ((long)(b * CIN + c) << 12);
    int r0 = (2 * i) * 64 + 2 * j;
    g_x1t[idx] = tf32r(0.25f * (xb[r0] + xb[r0 + 1] + xb[r0 + 64] + xb[r0 + 65]));
}

__global__ void zero_k() {
    int i = blockIdx.x * 256 + threadIdx.x;
    if (i < 2 * B_ * CDIM_ * KK_) g_out[i] = 0.f;
}

// prep per-scale: concat+convert w1 weights, convert w2f/w2s, copy biases
__global__ void prep_k(int s,
                       const float* __restrict__ fw1, const float* __restrict__ fb1,
                       const float* __restrict__ sw1, const float* __restrict__ sb1,
                       const float* __restrict__ dw1, const float* __restrict__ db1,
                       const float* __restrict__ fw2, const float* __restrict__ sw2) {
    int idx = blockIdx.x * 256 + threadIdx.x;
    float* wb = g_wbuf + (long)s * WSTRIDE;
    const int A1 = 512 * CIN, A2 = 1024 * CIN;
    if (idx < W1SZ) {
        float v;
        if (idx < A1) v = fw1[idx];
        else if (idx < A2) v = sw1[idx - A1];
        else v = dw1[idx - A2];
        wb[idx] = tf32r(v);
    }
    if (idx < W2FSZ) wb[W1SZ + idx] = tf32r(fw2[idx]);
    if (idx < W2SSZ) wb[W1SZ + W2FSZ + idx] = tf32r(sw2[idx]);
    if (idx < 1152)
        g_bbuf[s * 1152 + idx] =
            (idx < 512) ? fb1[idx] : (idx < 1024) ? sb1[idx - 512] : db1[idx - 1024];
}

// -------- cp.async helpers --------
__device__ __forceinline__ void cp_async16(void* smem, const void* gmem, bool pred) {
    unsigned saddr = (unsigned)__cvta_generic_to_shared(smem);
    int sz = pred ? 16 : 0;
    asm volatile("cp.async.cg.shared.global [%0], [%1], 16, %2;\n"
                 :: "r"(saddr), "l"(gmem), "r"(sz));
}
__device__ __forceinline__ void cp_commit() { asm volatile("cp.async.commit_group;\n"); }
__device__ __forceinline__ void cp_wait0()  { asm volatile("cp.async.wait_group 0;\n"); }
__device__ __forceinline__ void cp_wait1()  { asm volatile("cp.async.wait_group 1;\n"); }

// -------- tf32 tensor-core GEMM (inputs pre-rounded to tf32 bits) --------
// MODE: 0 = plain fp32 store, 1 = relu + tf32-round store, 2 = exp store
template <int MODE>
__global__ void __launch_bounds__(256)
tgemm(long woff, const float* __restrict__ biasp, long boff,
      int xid, long xoff, int cid, long coff, int M, int K, int L) {
    const float* W = g_wbuf + woff;
    const float* bias = biasp ? biasp : (g_bbuf + boff);
    const float* X = bufptr(xid) + xoff;
    float* C = bufptr(cid) + coff;

    __shared__ float sA[2][128 * 20];
    __shared__ float sB[2][16 * 136];

    int tid = threadIdx.x;
    int lane = tid & 31, warp = tid >> 5;
    int wm = warp >> 1, wn = warp & 1;
    int g = lane >> 2, tg = lane & 3;
    int bm = blockIdx.x * 128, bl = blockIdx.y * 128;

    float acc[2][8][4];
#pragma unroll
    for (int mt = 0; mt < 2; mt++)
#pragma unroll
        for (int nt = 0; nt < 8; nt++)
#pragma unroll
            for (int i = 0; i < 4; i++) acc[mt][nt][i] = 0.f;

    int ntiles = K / BK;

#define PREFETCH(kt, buf)                                                          \
    {                                                                              \
        _Pragma("unroll")                                                          \
        for (int i = 0; i < 2; i++) {                                              \
            int f = tid + i * 256;                                                 \
            int m = f >> 2, kq = f & 3;                                            \
            int r = bm + m;                                                        \
            bool p = r < M;                                                        \
            int rs = p ? r : (M - 1);                                              \
            cp_async16(&sA[buf][m * 20 + kq * 4],                                  \
                       W + (long)rs * K + (kt) * BK + kq * 4, p);                  \
        }                                                                          \
        _Pragma("unroll")                                                          \
        for (int i = 0; i < 2; i++) {                                              \
            int f = tid + i * 256;                                                 \
            int k = f >> 5, nq = f & 31;                                           \
            cp_async16(&sB[buf][k * 136 + nq * 4],                                 \
                       X + (long)((kt) * BK + k) * L + bl + nq * 4, true);         \
        }                                                                          \
        cp_commit();                                                               \
    }

    PREFETCH(0, 0);

    for (int kt = 0; kt < ntiles; kt++) {
        int buf = kt & 1;
        if (kt + 1 < ntiles) {
            PREFETCH(kt + 1, buf ^ 1);
            cp_wait1();
        } else {
            cp_wait0();
        }
        __syncthreads();

        const float* A = sA[buf];
        const float* Bm = sB[buf];
#pragma unroll
        for (int ks = 0; ks < 2; ks++) {
            int k0 = ks * 8;
            unsigned a[2][4];
#pragma unroll
            for (int mt = 0; mt < 2; mt++) {
                int m0 = wm * 32 + mt * 16 + g;
                a[mt][0] = __float_as_uint(A[m0 * 20 + k0 + tg]);
                a[mt][1] = __float_as_uint(A[(m0 + 8) * 20 + k0 + tg]);
                a[mt][2] = __float_as_uint(A[m0 * 20 + k0 + tg + 4]);
                a[mt][3] = __float_as_uint(A[(m0 + 8) * 20 + k0 + tg + 4]);
            }
            unsigned bfr[8][2];
#pragma unroll
            for (int nt = 0; nt < 8; nt++) {
                int n0 = wn * 64 + nt * 8 + g;
                bfr[nt][0] = __float_as_uint(Bm[(k0 + tg) * 136 + n0]);
                bfr[nt][1] = __float_as_uint(Bm[(k0 + tg + 4) * 136 + n0]);
            }
#pragma unroll
            for (int mt = 0; mt < 2; mt++)
#pragma unroll
                for (int nt = 0; nt < 8; nt++) {
                    asm volatile(
                        "mma.sync.aligned.m16n8k8.row.col.f32.tf32.tf32.f32 "
                        "{%0,%1,%2,%3}, {%4,%5,%6,%7}, {%8,%9}, {%0,%1,%2,%3};\n"
                        : "+f"(acc[mt][nt][0]), "+f"(acc[mt][nt][1]),
                          "+f"(acc[mt][nt][2]), "+f"(acc[mt][nt][3])
                        : "r"(a[mt][0]), "r"(a[mt][1]), "r"(a[mt][2]), "r"(a[mt][3]),
                          "r"(bfr[nt][0]), "r"(bfr[nt][1]));
                }
        }
        __syncthreads();
    }
#undef PREFETCH

#pragma unroll
    for (int mt = 0; mt < 2; mt++) {
        int r0 = bm + wm * 32 + mt * 16 + g;
        int r1 = r0 + 8;
        float bv0 = (r0 < M) ? bias[r0] : 0.f;
        float bv1 = (r1 < M) ? bias[r1] : 0.f;
#pragma unroll
        for (int nt = 0; nt < 8; nt++) {
            int cc = bl + wn * 64 + nt * 8 + tg * 2;
            if (r0 < M) {
                float2 v;
                v.x = acc[mt][nt][0] + bv0;
                v.y = acc[mt][nt][1] + bv0;
                if (MODE == 1) { v.x = tf32r(fmaxf(v.x, 0.f)); v.y = tf32r(fmaxf(v.y, 0.f)); }
                if (MODE == 2) { v.x = __expf(v.x); v.y = __expf(v.y); }
                *(float2*)&C[(long)r0 * L + cc] = v;
            }
            if (r1 < M) {
                float2 v;
                v.x = acc[mt][nt][2] + bv1;
                v.y = acc[mt][nt][3] + bv1;
                if (MODE == 1) { v.x = tf32r(fmaxf(v.x, 0.f)); v.y = tf32r(fmaxf(v.y, 0.f)); }
                if (MODE == 2) { v.x = __expf(v.x); v.y = __expf(v.y); }
                *(float2*)&C[(long)r1 * L + cc] = v;
            }
        }
    }
}

// -------- dustbin: E[64, l] = exp(db2 + dw2 . hidden_d[:, l]) --------
__global__ void dustbin_k(const float* __restrict__ dw2, const float* __restrict__ db2, int L) {
    __shared__ float w[128];
    int tid = threadIdx.x;
    if (tid < 128) w[tid] = dw2[tid];
    __syncthreads();
    long l = (long)blockIdx.x * 256 + tid;
    const float* h = g_hidden + (long)1024 * L + l;
    float acc = db2[0];
#pragma unroll 8
    for (int k = 0; k < 128; k++) acc += w[k] * h[(long)k * L];
    g_Z[(long)64 * L + l] = __expf(acc);
}

// -------- Sinkhorn in exp space (3 iters), outputs c_n --------
__global__ void __launch_bounds__(1024) sinkhorn_k(int N, int L) {
    int b = blockIdx.x;
    __shared__ float c[4096];
    __shared__ float r[72];
    int tid = threadIdx.x;
    int lane = tid & 31, warp = tid >> 5;
    float mu = 1.0f / 65.0f;
    float nu = 1.0f / (float)N;
    long zb = (long)b * N;

    for (int n = tid; n < N; n += 1024) c[n] = 1.f;
    __syncthreads();

    for (int it = 0; it < 3; it++) {
        // r-step: warp per row k
        for (int k = warp; k < 65; k += 32) {
            float s = 0.f;
            const float* er = g_Z + (long)k * L + zb;
            for (int n = lane; n < N; n += 32) s += er[n] * c[n];
#pragma unroll
            for (int off = 16; off; off >>= 1) s += __shfl_xor_sync(0xffffffffu, s, off);
            if (lane == 0) r[k] = mu / s;
        }
        __syncthreads();
        // c-step: thread per column
        for (int n = tid; n < N; n += 1024) {
            float s = 0.f;
            const float* ec = g_Z + zb + n;
#pragma unroll 13
            for (int k = 0; k < 65; k++) s += ec[(long)k * L] * r[k];
            c[n] = nu / s;
        }
        __syncthreads();
    }
    for (int n = tid; n < N; n += 1024) g_c[zb + n] = c[n];
}

// -------- einsum: out[b,c,k] += sum_n feat[c,n] * E[k,n] * cn[n] --------
__global__ void __launch_bounds__(256) einsum_k(int scale, int N, int L) {
    int b = blockIdx.x;
    int nc0 = blockIdx.y * 128;
    __shared__ float Fs[32][132];
    __shared__ float Ps[32][68];
    int tid = threadIdx.x, tx = tid & 15, ty = tid >> 4;
    long base = (long)b * N;

    float acc[8][4];
#pragma unroll
    for (int i = 0; i < 8; i++)
#pragma unroll
        for (int j = 0; j < 4; j++) acc[i][j] = 0.f;

    for (int nc = nc0; nc < nc0 + 128; nc += 32) {
#pragma unroll
        for (int i = 0; i < 16; i++) {
            int e = tid + i * 256;
            int cch = e >> 5, n = e & 31;
            Fs[n][cch] = g_feat[(long)cch * L + base + nc + n];
        }
        {
            int n = tid & 31;
            float cv = g_c[base + nc + n];
#pragma unroll
            for (int i = 0; i < 8; i++) {
                int e = tid + i * 256;
                int k = e >> 5;
                Ps[n][k] = g_Z[(long)k * L + base + nc + n] * cv;
            }
        }
        __syncthreads();
#pragma unroll
        for (int kk = 0; kk < 32; kk++) {
            float a[8], bb[4];
            float4 t;
            t = *(const float4*)&Fs[kk][ty * 4];      a[0]=t.x; a[1]=t.y; a[2]=t.z; a[3]=t.w;
            t = *(const float4*)&Fs[kk][ty * 4 + 64]; a[4]=t.x; a[5]=t.y; a[6]=t.z; a[7]=t.w;
            t = *(const float4*)&Ps[kk][tx * 4];      bb[0]=t.x; bb[1]=t.y; bb[2]=t.z; bb[3]=t.w;
#pragma unroll
            for (int i = 0; i < 8; i++)
#pragma unroll
                for (int j = 0; j < 4; j++) acc[i][j] += a[i] * bb[j];
        }
        __syncthreads();
    }

    float* outp = g_out + ((long)scale * B_ + b) * (CDIM_ * KK_);
#pragma unroll
    for (int i = 0; i < 8; i++) {
        int rr = (i < 4) ? (ty * 4 + i) : (64 + ty * 4 + i - 4);
#pragma unroll
        for (int j = 0; j < 4; j++)
            atomicAdd(&outp[rr * 64 + tx * 4 + j], acc[i][j]);
    }
}

// -------- final normalization --------
__global__ void __launch_bounds__(256) final_k(float* __restrict__ out) {
    int b = blockIdx.x, tid = threadIdx.x;
    __shared__ float d[8192];
    __shared__ float cn[2][64];
    __shared__ float red[9];
    if (tid < 128) cn[tid >> 6][tid & 63] = 0.f;
    __syncthreads();
    const float* o0 = g_out + (long)b * 8192;
    const float* o1 = g_out + (long)(B_ + b) * 8192;
    for (int e = tid; e < 8192; e += 256) {
        float v0 = o0[e], v1 = o1[e];
        atomicAdd(&cn[0][e & 63], v0 * v0);
        atomicAdd(&cn[1][e & 63], v1 * v1);
    }
    __syncthreads();
    if (tid < 128) {
        float nn = sqrtf(cn[tid >> 6][tid & 63]);
        cn[tid >> 6][tid & 63] = 1.f / fmaxf(nn, 1e-12f);
    }
    __syncthreads();
    float ss = 0.f;
    for (int e = tid; e < 8192; e += 256) {
        int k = e & 63;
        float dv = 0.5f * (o0[e] * cn[0][k] + o1[e] * cn[1][k]);
        d[e] = dv;
        ss += dv * dv;
    }
#pragma unroll
    for (int off = 16; off; off >>= 1) ss += __shfl_xor_sync(0xffffffffu, ss, off);
    if ((tid & 31) == 0) red[tid >> 5] = ss;
    __syncthreads();
    if (tid == 0) {
        float t = 0.f;
        for (int i = 0; i < 8; i++) t += red[i];
        red[8] = 1.f / fmaxf(sqrtf(t), 1e-12f);
    }
    __syncthreads();
    float inv = red[8];
    for (int e = tid; e < 8192; e += 256) out[(long)b * 8192 + e] = d[e] * inv;
}

extern "C" void kernel_launch(void* const* d_in, const int* in_sizes, int n_in,
                              void* d_out, int out_size) {
    (void)in_sizes; (void)n_in; (void)out_size;
    const float* x = (const float*)d_in[0];

    // launch order chosen so launch #5 (ncu -s 5 -c 1) is the big L1 GEMM
    zero_k<<<1024, 256>>>();
    transpose_k<<<(CIN * L0) / 256, 256>>>(x);
    pool_k<<<(CIN * L1) / 256, 256>>>(x);
    for (int s = 0; s < 2; s++) {
        int base = 1 + s * 12;
        prep_k<<<1728, 256>>>(s,
            (const float*)d_in[base + 0], (const float*)d_in[base + 1],
            (const float*)d_in[base + 4], (const float*)d_in[base + 5],
            (const float*)d_in[base + 8], (const float*)d_in[base + 9],
            (const float*)d_in[base + 2], (const float*)d_in[base + 6]);
    }

    for (int s = 0; s < 2; s++) {
        int base = 1 + s * 12;
        const float* fb2 = (const float*)d_in[base + 3];
        const float* sb2 = (const float*)d_in[base + 7];
        const float* dw2 = (const float*)d_in[base + 10];
        const float* db2 = (const float*)d_in[base + 11];

        int L = s ? L1 : L0;
        int N = s ? N1_ : N0_;
        int xid = s ? 1 : 0;
        long ws = (long)s * WSTRIDE;

        // fused layer-1 (relu, tf32-rounded store)
        tgemm<1><<<dim3(9, L / 128), 256>>>(ws, nullptr, (long)s * 1152,
                                            xid, 0L, 2, 0L, 1152, CIN, L);
        // layer-2 feat (plain fp32)
        tgemm<0><<<dim3(1, L / 128), 256>>>(ws + W1SZ, fb2, 0L,
                                            2, 0L, 3, 0L, CDIM_, 512, L);
        // layer-2 score (exp store -> E)
        tgemm<2><<<dim3(1, L / 128), 256>>>(ws + W1SZ + W2FSZ, sb2, 0L,
                                            2, (long)512 * L, 4, 0L, KK_, 512, L);
        dustbin_k<<<L / 256, 256>>>(dw2, db2, L);

        sinkhorn_k<<<B_, 1024>>>(N, L);
        einsum_k<<<dim3(B_, N / 128), 256>>>(s, N, L);
    }

    final_k<<<B_, 256>>>((float*)d_out);
}

// round 6
// speedup vs baseline: 1.3642x; 1.3642x over previous
#include <cuda_runtime.h>
#include <cuda_fp16.h>
#include <math.h>

// Problem constants
#define B_    16
#define CIN   384
#define L0    65536   // B * 64*64
#define L1    16384   // B * 32*32
#define N0_   4096
#define N1_   1024
#define CDIM_ 128
#define KK_   64

// weight buffer layout per scale: w1[1152*384] | w2f[128*512] | w2s_padded[128*512]
#define W1SZ  (1152 * CIN)
#define W2FSZ (128 * 512)
#define W2SSZ (128 * 512)
#define WSTRIDE (W1SZ + W2FSZ + W2SSZ)

// -------- scratch (device globals; no allocation allowed) --------
__device__ __half g_xt  [CIN * L0];       // x transposed, fp16 [C, B*N0]
__device__ __half g_x1t [CIN * L1];       // pooled x, fp16 [C, B*N1]
__device__ __half g_hidden[1152 * L0];    // relu(hidden), fp16
__device__ float  g_feat[CDIM_ * L0];     // local_feat fp32 [128, L]
__device__ float  g_Z   [65 * L0];        // E = exp(scores|dustbin) [65, L]
__device__ float  g_out [2 * B_ * CDIM_ * KK_];
__device__ __half g_wbuf[2 * WSTRIDE];    // fp16 weights per scale
__device__ float  g_bbuf[2 * 1152];       // layer-1 biases per scale
__device__ float  g_c   [B_ * N0_];       // sinkhorn column scaling c_n

__device__ __forceinline__ const __half* xptr(int id) {
    return id == 0 ? g_xt : (id == 1 ? g_x1t : g_hidden);
}

// -------- layout transforms (store fp16) --------
__global__ void transpose_k(const float* __restrict__ x) {
    int idx = blockIdx.x * 256 + threadIdx.x;
    int c = idx >> 16;
    int l = idx & 65535;
    int b = l >> 12;
    int n = l & 4095;
    g_xt[idx] = __float2half_rn(x[((long)(b * CIN + c) << 12) + n]);
}

__global__ void pool_k(const float* __restrict__ x) {
    int idx = blockIdx.x * 256 + threadIdx.x;
    int c = idx >> 14;
    int l = idx & 16383;
    int b = l >> 10;
    int p = l & 1023;
    int i = p >> 5, j = p & 31;
    const float* xb = x + ((long)(b * CIN + c) << 12);
    int r0 = (2 * i) * 64 + 2 * j;
    g_x1t[idx] = __float2half_rn(0.25f * (xb[r0] + xb[r0 + 1] + xb[r0 + 64] + xb[r0 + 65]));
}

__global__ void zero_k() {
    int i = blockIdx.x * 256 + threadIdx.x;
    if (i < 2 * B_ * CDIM_ * KK_) g_out[i] = 0.f;
}

// prep per-scale: concat+convert w1, convert w2f, convert+zero-pad w2s (64->128 rows)
__global__ void prep_k(int s,
                       const float* __restrict__ fw1, const float* __restrict__ fb1,
                       const float* __restrict__ sw1, const float* __restrict__ sb1,
                       const float* __restrict__ dw1, const float* __restrict__ db1,
                       const float* __restrict__ fw2, const float* __restrict__ sw2) {
    int idx = blockIdx.x * 256 + threadIdx.x;
    __half* wb = g_wbuf + (long)s * WSTRIDE;
    const int A1 = 512 * CIN, A2 = 1024 * CIN;
    if (idx < W1SZ) {
        float v;
        if (idx < A1) v = fw1[idx];
        else if (idx < A2) v = sw1[idx - A1];
        else v = dw1[idx - A2];
        wb[idx] = __float2half_rn(v);
    }
    if (idx < W2FSZ) wb[W1SZ + idx] = __float2half_rn(fw2[idx]);
    if (idx < W2SSZ) {
        int row = idx >> 9;
        wb[W1SZ + W2FSZ + idx] = __float2half_rn((row < 64) ? sw2[idx] : 0.f);
    }
    if (idx < 1152)
        g_bbuf[s * 1152 + idx] =
            (idx < 512) ? fb1[idx] : (idx < 1024) ? sb1[idx - 512] : db1[idx - 1024];
}

// -------- async / ldmatrix helpers --------
__device__ __forceinline__ void cp16s(unsigned saddr, const void* g) {
    asm volatile("cp.async.cg.shared.global [%0], [%1], 16;\n" :: "r"(saddr), "l"(g));
}
__device__ __forceinline__ void cp_commit() { asm volatile("cp.async.commit_group;\n"); }
__device__ __forceinline__ void cp_wait0()  { asm volatile("cp.async.wait_group 0;\n"); }
__device__ __forceinline__ void cp_wait1()  { asm volatile("cp.async.wait_group 1;\n"); }

__device__ __forceinline__ void ldsm_x4(unsigned* r, unsigned addr) {
    asm volatile("ldmatrix.sync.aligned.m8n8.x4.shared.b16 {%0,%1,%2,%3}, [%4];"
                 : "=r"(r[0]), "=r"(r[1]), "=r"(r[2]), "=r"(r[3]) : "r"(addr));
}
__device__ __forceinline__ void ldsm_x2t(unsigned* r, unsigned addr) {
    asm volatile("ldmatrix.sync.aligned.m8n8.x2.trans.shared.b16 {%0,%1}, [%2];"
                 : "=r"(r[0]), "=r"(r[1]) : "r"(addr));
}

// -------- fp16 tensor-core GEMM: C[M,L] = W[M,K] @ X[K,L] (+bias, epilogue) --------
// 128x128 tile, BK=16, 256 threads = 8 warps (4m x 2n), warp tile 32m x 64n.
// MODE: 0 = plain fp32 store, 1 = relu + fp16 store, 2 = exp fp32 store.
template <int MODE>
__global__ void __launch_bounds__(256)
hgemm(long woff, const float* __restrict__ biasp, long boff,
      int xid, long xoff, int cid, long coff, int K, int L, int Mstore) {
    const __half* W = g_wbuf + woff;
    const float* bias = biasp ? biasp : (g_bbuf + boff);
    const __half* X = xptr(xid) + xoff;
    __half* Ch = g_hidden + coff;
    float* Cf = ((cid == 3) ? g_feat : g_Z) + coff;

    __shared__ __half sA[2][128 * 24];
    __shared__ __half sB[2][16 * 136];

    int tid = threadIdx.x, lane = tid & 31, warp = tid >> 5;
    int wm = warp >> 1, wn = warp & 1;
    int g = lane >> 2, tg = lane & 3;
    int bm = blockIdx.x * 128;
    long bl = (long)blockIdx.y * 128;

    unsigned aB0 = (unsigned)__cvta_generic_to_shared(&sA[0][0]);
    unsigned aB1 = (unsigned)__cvta_generic_to_shared(&sA[1][0]);
    unsigned bB0 = (unsigned)__cvta_generic_to_shared(&sB[0][0]);
    unsigned bB1 = (unsigned)__cvta_generic_to_shared(&sB[1][0]);

    float acc[2][8][4];
#pragma unroll
    for (int mt = 0; mt < 2; mt++)
#pragma unroll
        for (int n = 0; n < 8; n++)
#pragma unroll
            for (int i = 0; i < 4; i++) acc[mt][n][i] = 0.f;

    int ntiles = K / 16;

#define PREFETCH(kt, buf)                                                        \
    {                                                                            \
        unsigned aS = (buf) ? aB1 : aB0;                                         \
        unsigned bS = (buf) ? bB1 : bB0;                                         \
        int m = tid >> 1, q = tid & 1;                                           \
        cp16s(aS + (unsigned)(m * 24 + q * 8) * 2u,                              \
              W + (long)(bm + m) * K + (kt) * 16 + q * 8);                       \
        int k = tid >> 4, n8 = tid & 15;                                         \
        cp16s(bS + (unsigned)(k * 136 + n8 * 8) * 2u,                            \
              X + (long)((kt) * 16 + k) * L + bl + n8 * 8);                      \
        cp_commit();                                                             \
    }

    PREFETCH(0, 0);

    for (int kt = 0; kt < ntiles; kt++) {
        int buf = kt & 1;
        if (kt + 1 < ntiles) {
            PREFETCH(kt + 1, buf ^ 1);
            cp_wait1();
        } else {
            cp_wait0();
        }
        __syncthreads();

        unsigned aS = buf ? aB1 : aB0;
        unsigned bS = buf ? bB1 : bB0;

        unsigned ra[2][4];
        {
            int rbase = (lane & 7) + ((lane >> 3) & 1) * 8;
            int kof = (lane >> 4) * 8;
#pragma unroll
            for (int mt = 0; mt < 2; mt++) {
                int row = wm * 32 + mt * 16 + rbase;
                ldsm_x4(ra[mt], aS + (unsigned)(row * 24 + kof) * 2u);
            }
        }
        unsigned rb[8][2];
        {
            int kk = lane & 15;
#pragma unroll
            for (int n = 0; n < 8; n++) {
                int n0 = wn * 64 + n * 8;
                ldsm_x2t(rb[n], bS + (unsigned)(kk * 136 + n0) * 2u);
            }
        }
#pragma unroll
        for (int mt = 0; mt < 2; mt++)
#pragma unroll
            for (int n = 0; n < 8; n++) {
                asm volatile(
                    "mma.sync.aligned.m16n8k16.row.col.f32.f16.f16.f32 "
                    "{%0,%1,%2,%3}, {%4,%5,%6,%7}, {%8,%9}, {%0,%1,%2,%3};\n"
                    : "+f"(acc[mt][n][0]), "+f"(acc[mt][n][1]),
                      "+f"(acc[mt][n][2]), "+f"(acc[mt][n][3])
                    : "r"(ra[mt][0]), "r"(ra[mt][1]), "r"(ra[mt][2]), "r"(ra[mt][3]),
                      "r"(rb[n][0]), "r"(rb[n][1]));
            }
        __syncthreads();
    }
#undef PREFETCH

    // epilogue
#pragma unroll
    for (int mt = 0; mt < 2; mt++) {
        int r0 = bm + wm * 32 + mt * 16 + g;
        int r1 = r0 + 8;
        float bv0 = (r0 < Mstore) ? bias[r0] : 0.f;
        float bv1 = (r1 < Mstore) ? bias[r1] : 0.f;
#pragma unroll
        for (int n = 0; n < 8; n++) {
            long cc = bl + wn * 64 + n * 8 + tg * 2;
            if (r0 < Mstore) {
                float vx = acc[mt][n][0] + bv0;
                float vy = acc[mt][n][1] + bv0;
                if (MODE == 1) {
                    *(__half2*)&Ch[(long)r0 * L + cc] =
                        __floats2half2_rn(fmaxf(vx, 0.f), fmaxf(vy, 0.f));
                } else {
                    float2 v;
                    v.x = (MODE == 2) ? __expf(vx) : vx;
                    v.y = (MODE == 2) ? __expf(vy) : vy;
                    *(float2*)&Cf[(long)r0 * L + cc] = v;
                }
            }
            if (r1 < Mstore) {
                float vx = acc[mt][n][2] + bv1;
                float vy = acc[mt][n][3] + bv1;
                if (MODE == 1) {
                    *(__half2*)&Ch[(long)r1 * L + cc] =
                        __floats2half2_rn(fmaxf(vx, 0.f), fmaxf(vy, 0.f));
                } else {
                    float2 v;
                    v.x = (MODE == 2) ? __expf(vx) : vx;
                    v.y = (MODE == 2) ? __expf(vy) : vy;
                    *(float2*)&Cf[(long)r1 * L + cc] = v;
                }
            }
        }
    }
}

// -------- dustbin: E[64, l] = exp(db2 + dw2 . hidden_d[:, l]) --------
__global__ void dustbin_k(const float* __restrict__ dw2, const float* __restrict__ db2, int L) {
    __shared__ float w[128];
    int tid = threadIdx.x;
    if (tid < 128) w[tid] = dw2[tid];
    __syncthreads();
    long l = (long)blockIdx.x * 256 + tid;
    const __half* h = g_hidden + (long)1024 * L + l;
    float acc = db2[0];
#pragma unroll 8
    for (int k = 0; k < 128; k++) acc += w[k] * __half2float(h[(long)k * L]);
    g_Z[(long)64 * L + l] = __expf(acc);
}

// -------- Sinkhorn in exp space (3 iters), outputs c_n --------
__global__ void __launch_bounds__(1024) sinkhorn_k(int N, int L) {
    int b = blockIdx.x;
    __shared__ float c[4096];
    __shared__ float r[72];
    int tid = threadIdx.x;
    int lane = tid & 31, warp = tid >> 5;
    float mu = 1.0f / 65.0f;
    float nu = 1.0f / (float)N;
    long zb = (long)b * N;

    for (int n = tid; n < N; n += 1024) c[n] = 1.f;
    __syncthreads();

    for (int it = 0; it < 3; it++) {
        for (int k = warp; k < 65; k += 32) {
            float s = 0.f;
            const float* er = g_Z + (long)k * L + zb;
            for (int n = lane; n < N; n += 32) s += er[n] * c[n];
#pragma unroll
            for (int off = 16; off; off >>= 1) s += __shfl_xor_sync(0xffffffffu, s, off);
            if (lane == 0) r[k] = mu / s;
        }
        __syncthreads();
        for (int n = tid; n < N; n += 1024) {
            float s = 0.f;
            const float* ec = g_Z + zb + n;
#pragma unroll 13
            for (int k = 0; k < 65; k++) s += ec[(long)k * L] * r[k];
            c[n] = nu / s;
        }
        __syncthreads();
    }
    for (int n = tid; n < N; n += 1024) g_c[zb + n] = c[n];
}

// -------- einsum: out[b,c,k] += sum_n feat[c,n] * E[k,n] * cn[n] --------
__global__ void __launch_bounds__(256) einsum_k(int scale, int N, int L) {
    int b = blockIdx.x;
    int nc0 = blockIdx.y * 128;
    __shared__ float Fs[32][132];
    __shared__ float Ps[32][68];
    int tid = threadIdx.x, tx = tid & 15, ty = tid >> 4;
    long base = (long)b * N;

    float acc[8][4];
#pragma unroll
    for (int i = 0; i < 8; i++)
#pragma unroll
        for (int j = 0; j < 4; j++) acc[i][j] = 0.f;

    for (int nc = nc0; nc < nc0 + 128; nc += 32) {
#pragma unroll
        for (int i = 0; i < 16; i++) {
            int e = tid + i * 256;
            int cch = e >> 5, n = e & 31;
            Fs[n][cch] = g_feat[(long)cch * L + base + nc + n];
        }
        {
            int n = tid & 31;
            float cv = g_c[base + nc + n];
#pragma unroll
            for (int i = 0; i < 8; i++) {
                int e = tid + i * 256;
                int k = e >> 5;
                Ps[n][k] = g_Z[(long)k * L + base + nc + n] * cv;
            }
        }
        __syncthreads();
#pragma unroll
        for (int kk = 0; kk < 32; kk++) {
            float a[8], bb[4];
            float4 t;
            t = *(const float4*)&Fs[kk][ty * 4];      a[0]=t.x; a[1]=t.y; a[2]=t.z; a[3]=t.w;
            t = *(const float4*)&Fs[kk][ty * 4 + 64]; a[4]=t.x; a[5]=t.y; a[6]=t.z; a[7]=t.w;
            t = *(const float4*)&Ps[kk][tx * 4];      bb[0]=t.x; bb[1]=t.y; bb[2]=t.z; bb[3]=t.w;
#pragma unroll
            for (int i = 0; i < 8; i++)
#pragma unroll
                for (int j = 0; j < 4; j++) acc[i][j] += a[i] * bb[j];
        }
        __syncthreads();
    }

    float* outp = g_out + ((long)scale * B_ + b) * (CDIM_ * KK_);
#pragma unroll
    for (int i = 0; i < 8; i++) {
        int rr = (i < 4) ? (ty * 4 + i) : (64 + ty * 4 + i - 4);
#pragma unroll
        for (int j = 0; j < 4; j++)
            atomicAdd(&outp[rr * 64 + tx * 4 + j], acc[i][j]);
    }
}

// -------- final normalization --------
__global__ void __launch_bounds__(256) final_k(float* __restrict__ out) {
    int b = blockIdx.x, tid = threadIdx.x;
    __shared__ float d[8192];
    __shared__ float cn[2][64];
    __shared__ float red[9];
    if (tid < 128) cn[tid >> 6][tid & 63] = 0.f;
    __syncthreads();
    const float* o0 = g_out + (long)b * 8192;
    const float* o1 = g_out + (long)(B_ + b) * 8192;
    for (int e = tid; e < 8192; e += 256) {
        float v0 = o0[e], v1 = o1[e];
        atomicAdd(&cn[0][e & 63], v0 * v0);
        atomicAdd(&cn[1][e & 63], v1 * v1);
    }
    __syncthreads();
    if (tid < 128) {
        float nn = sqrtf(cn[tid >> 6][tid & 63]);
        cn[tid >> 6][tid & 63] = 1.f / fmaxf(nn, 1e-12f);
    }
    __syncthreads();
    float ss = 0.f;
    for (int e = tid; e < 8192; e += 256) {
        int k = e & 63;
        float dv = 0.5f * (o0[e] * cn[0][k] + o1[e] * cn[1][k]);
        d[e] = dv;
        ss += dv * dv;
    }
#pragma unroll
    for (int off = 16; off; off >>= 1) ss += __shfl_xor_sync(0xffffffffu, ss, off);
    if ((tid & 31) == 0) red[tid >> 5] = ss;
    __syncthreads();
    if (tid == 0) {
        float t = 0.f;
        for (int i = 0; i < 8; i++) t += red[i];
        red[8] = 1.f / fmaxf(sqrtf(t), 1e-12f);
    }
    __syncthreads();
    float inv = red[8];
    for (int e = tid; e < 8192; e += 256) out[(long)b * 8192 + e] = d[e] * inv;
}

extern "C" void kernel_launch(void* const* d_in, const int* in_sizes, int n_in,
                              void* d_out, int out_size) {
    (void)in_sizes; (void)n_in; (void)out_size;
    const float* x = (const float*)d_in[0];

    for (int s = 0; s < 2; s++) {
        int base = 1 + s * 12;
        prep_k<<<1728, 256>>>(s,
            (const float*)d_in[base + 0], (const float*)d_in[base + 1],
            (const float*)d_in[base + 4], (const float*)d_in[base + 5],
            (const float*)d_in[base + 8], (const float*)d_in[base + 9],
            (const float*)d_in[base + 2], (const float*)d_in[base + 6]);
    }
    transpose_k<<<(CIN * L0) / 256, 256>>>(x);
    pool_k<<<(CIN * L1) / 256, 256>>>(x);
    zero_k<<<1024, 256>>>();

    for (int s = 0; s < 2; s++) {
        int base = 1 + s * 12;
        const float* fb2 = (const float*)d_in[base + 3];
        const float* sb2 = (const float*)d_in[base + 7];
        const float* dw2 = (const float*)d_in[base + 10];
        const float* db2 = (const float*)d_in[base + 11];

        int L = s ? L1 : L0;
        int N = s ? N1_ : N0_;
        int xid = s ? 1 : 0;
        long ws = (long)s * WSTRIDE;

        // fused layer-1 (relu + fp16 store): M=1152
        hgemm<1><<<dim3(9, L / 128), 256>>>(ws, nullptr, (long)s * 1152,
                                            xid, 0L, 2, 0L, CIN, L, 1152);
        // layer-2 feat (plain fp32): M=128
        hgemm<0><<<dim3(1, L / 128), 256>>>(ws + W1SZ, fb2, 0L,
                                            2, 0L, 3, 0L, 512, L, 128);
        // layer-2 score (exp store -> E): weights padded to 128 rows, store 64
        hgemm<2><<<dim3(1, L / 128), 256>>>(ws + W1SZ + W2FSZ, sb2, 0L,
                                            2, (long)512 * L, 4, 0L, 512, L, 64);
        dustbin_k<<<L / 256, 256>>>(dw2, db2, L);

        sinkhorn_k<<<B_, 1024>>>(N, L);
        einsum_k<<<dim3(B_, N / 128), 256>>>(s, N, L);
    }

    final_k<<<B_, 256>>>((float*)d_out);
}

// round 7
// speedup vs baseline: 1.7875x; 1.3103x over previous
#include <cuda_runtime.h>
#include <cuda_fp16.h>
#include <math.h>

// Problem constants
#define B_    16
#define CIN   384
#define L0    65536   // B * 64*64
#define L1    16384   // B * 32*32
#define N0_   4096
#define N1_   1024
#define CDIM_ 128
#define KK_   64

// weight buffer layout per scale: w1[1152*384] | w2f[128*512] | w2s[64*512 used]
#define W1SZ  (1152 * CIN)
#define W2FSZ (128 * 512)
#define W2SSZ (128 * 512)
#define WSTRIDE (W1SZ + W2FSZ + W2SSZ)

// -------- scratch (device globals; no allocation allowed) --------
__device__ __half g_xt  [CIN * L0];         // x transposed, fp16 [C, B*N0]
__device__ __half g_x1t [CIN * L1];         // pooled x, fp16 [C, B*N1]
__device__ __half g_hidden[1152 * L0];      // relu(hidden), fp16 (reused per scale)
__device__ __half g_feath[CDIM_ * (L0 + L1)];  // local_feat fp16, s0 | s1
__device__ float  g_Z   [65 * (L0 + L1)];   // E = exp(scores|dustbin), s0 | s1
__device__ float  g_out [2 * B_ * CDIM_ * KK_];
__device__ __half g_wbuf[2 * WSTRIDE];      // fp16 weights per scale
__device__ float  g_bbuf[2 * 1152];         // layer-1 biases per scale
__device__ float  g_c   [B_ * (N0_ + N1_)]; // sinkhorn column scaling, s0 | s1

__device__ __forceinline__ const __half* xptr(int id) {
    return id == 0 ? g_xt : (id == 1 ? g_x1t : g_hidden);
}

// -------- merged transpose + pool (x read once) --------
__global__ void tpose_pool_k(const float* __restrict__ x) {
    int idx = blockIdx.x * 256 + threadIdx.x;   // total 384*16384
    int c = idx >> 14;
    int l = idx & 16383;
    int b = l >> 10;
    int p = l & 1023;
    int i = p >> 5, j = p & 31;
    const float* xb = x + ((long)(b * CIN + c) << 12);
    int r0 = (2 * i) * 64 + 2 * j;
    float a0 = xb[r0], a1 = xb[r0 + 1], a2 = xb[r0 + 64], a3 = xb[r0 + 65];
    __half* xt = g_xt + ((long)c << 16) + (b << 12);
    *(__half2*)&xt[r0]      = __floats2half2_rn(a0, a1);
    *(__half2*)&xt[r0 + 64] = __floats2half2_rn(a2, a3);
    g_x1t[idx] = __float2half_rn(0.25f * (a0 + a1 + a2 + a3));
}

__global__ void zero_k() {
    int i = blockIdx.x * 256 + threadIdx.x;
    if (i < 2 * B_ * CDIM_ * KK_) g_out[i] = 0.f;
}

// prep per-scale: concat+convert w1, convert w2f, convert w2s (64 rows)
__global__ void prep_k(int s,
                       const float* __restrict__ fw1, const float* __restrict__ fb1,
                       const float* __restrict__ sw1, const float* __restrict__ sb1,
                       const float* __restrict__ dw1, const float* __restrict__ db1,
                       const float* __restrict__ fw2, const float* __restrict__ sw2) {
    int idx = blockIdx.x * 256 + threadIdx.x;
    __half* wb = g_wbuf + (long)s * WSTRIDE;
    const int A1 = 512 * CIN, A2 = 1024 * CIN;
    if (idx < W1SZ) {
        float v;
        if (idx < A1) v = fw1[idx];
        else if (idx < A2) v = sw1[idx - A1];
        else v = dw1[idx - A2];
        wb[idx] = __float2half_rn(v);
    }
    if (idx < W2FSZ) wb[W1SZ + idx] = __float2half_rn(fw2[idx]);
    if (idx < 64 * 512) wb[W1SZ + W2FSZ + idx] = __float2half_rn(sw2[idx]);
    if (idx < 1152)
        g_bbuf[s * 1152 + idx] =
            (idx < 512) ? fb1[idx] : (idx < 1024) ? sb1[idx - 512] : db1[idx - 1024];
}

// -------- async / ldmatrix helpers --------
__device__ __forceinline__ void cp16s(unsigned saddr, const void* g) {
    asm volatile("cp.async.cg.shared.global [%0], [%1], 16;\n" :: "r"(saddr), "l"(g));
}
__device__ __forceinline__ void cp_commit() { asm volatile("cp.async.commit_group;\n"); }
__device__ __forceinline__ void cp_wait0()  { asm volatile("cp.async.wait_group 0;\n"); }
__device__ __forceinline__ void cp_wait1()  { asm volatile("cp.async.wait_group 1;\n"); }

__device__ __forceinline__ void ldsm_x4(unsigned* r, unsigned addr) {
    asm volatile("ldmatrix.sync.aligned.m8n8.x4.shared.b16 {%0,%1,%2,%3}, [%4];"
                 : "=r"(r[0]), "=r"(r[1]), "=r"(r[2]), "=r"(r[3]) : "r"(addr));
}
__device__ __forceinline__ void ldsm_x2t(unsigned* r, unsigned addr) {
    asm volatile("ldmatrix.sync.aligned.m8n8.x2.trans.shared.b16 {%0,%1}, [%2];"
                 : "=r"(r[0]), "=r"(r[1]) : "r"(addr));
}

// -------- fp16 tensor-core GEMM: C[M,L] = W[M,K] @ X[K,L] (+bias, epilogue) --------
// CTA tile (MW*32) x 128, BK=32, 256 threads = 8 warps:
//   MW=4: warps 4m x 2n (warp 32m x 64n);  MW=2: warps 2m x 4n (warp 32m x 32n)
// MODE: 0 = bias, fp16 store (feat); 1 = relu, fp16 store (hidden); 2 = exp, fp32 store (E)
template <int MODE, int MW>
__global__ void __launch_bounds__(256)
hgemm(long woff, const float* __restrict__ biasp, long boff,
      int xid, long xoff, long coff, int K, int L, int Mstore) {
    constexpr int NT = (MW == 4) ? 8 : 4;
    const __half* W = g_wbuf + woff;
    const float* bias = biasp ? biasp : (g_bbuf + boff);
    const __half* X = xptr(xid) + xoff;
    __half* Ch = ((MODE == 0) ? g_feath : g_hidden) + coff;
    float* Cf = g_Z + coff;

    __shared__ __half sA[2][MW * 32 * 40];
    __shared__ __half sB[2][32 * 136];

    int tid = threadIdx.x, lane = tid & 31, warp = tid >> 5;
    int wm = (MW == 4) ? (warp >> 1) : (warp >> 2);
    int wn = (MW == 4) ? (warp & 1) : (warp & 3);
    int g = lane >> 2, tg = lane & 3;
    int bm = blockIdx.x * (MW * 32);
    long bl = (long)blockIdx.y * 128;

    unsigned aB0 = (unsigned)__cvta_generic_to_shared(&sA[0][0]);
    unsigned aB1 = (unsigned)__cvta_generic_to_shared(&sA[1][0]);
    unsigned bB0 = (unsigned)__cvta_generic_to_shared(&sB[0][0]);
    unsigned bB1 = (unsigned)__cvta_generic_to_shared(&sB[1][0]);

    float acc[2][NT][4];
#pragma unroll
    for (int mt = 0; mt < 2; mt++)
#pragma unroll
        for (int n = 0; n < NT; n++)
#pragma unroll
            for (int i = 0; i < 4; i++) acc[mt][n][i] = 0.f;

    int ntiles = K / 32;

#define PREFETCH(kt, buf)                                                        \
    {                                                                            \
        unsigned aS = (buf) ? aB1 : aB0;                                         \
        unsigned bS = (buf) ? bB1 : bB0;                                         \
        _Pragma("unroll")                                                        \
        for (int i = 0; i < MW / 2; i++) {                                       \
            int ch = tid + i * 256;                                              \
            int m = ch >> 2, q = ch & 3;                                         \
            cp16s(aS + (unsigned)(m * 40 + q * 8) * 2u,                          \
                  W + (long)(bm + m) * K + (kt) * 32 + q * 8);                   \
        }                                                                        \
        _Pragma("unroll")                                                        \
        for (int i = 0; i < 2; i++) {                                            \
            int ch = tid + i * 256;                                              \
            int k = ch >> 4, n8 = ch & 15;                                       \
            cp16s(bS + (unsigned)(k * 136 + n8 * 8) * 2u,                        \
                  X + (long)((kt) * 32 + k) * L + bl + n8 * 8);                  \
        }                                                                        \
        cp_commit();                                                             \
    }

    PREFETCH(0, 0);

    for (int kt = 0; kt < ntiles; kt++) {
        int buf = kt & 1;
        if (kt + 1 < ntiles) {
            PREFETCH(kt + 1, buf ^ 1);
            cp_wait1();
        } else {
            cp_wait0();
        }
        __syncthreads();

        unsigned aS = buf ? aB1 : aB0;
        unsigned bS = buf ? bB1 : bB0;
        int rbase = (lane & 7) + ((lane >> 3) & 1) * 8;
        int kof = (lane >> 4) * 8;

#pragma unroll
        for (int ks = 0; ks < 2; ks++) {
            unsigned ra[2][4];
#pragma unroll
            for (int mt = 0; mt < 2; mt++) {
                int row = wm * 32 + mt * 16 + rbase;
                ldsm_x4(ra[mt], aS + (unsigned)(row * 40 + ks * 16 + kof) * 2u);
            }
            unsigned rb[NT][2];
            int kk = ks * 16 + (lane & 15);
#pragma unroll
            for (int n = 0; n < NT; n++) {
                int n0 = wn * (NT * 8) + n * 8;
                ldsm_x2t(rb[n], bS + (unsigned)(kk * 136 + n0) * 2u);
            }
#pragma unroll
            for (int mt = 0; mt < 2; mt++)
#pragma unroll
                for (int n = 0; n < NT; n++) {
                    asm volatile(
                        "mma.sync.aligned.m16n8k16.row.col.f32.f16.f16.f32 "
                        "{%0,%1,%2,%3}, {%4,%5,%6,%7}, {%8,%9}, {%0,%1,%2,%3};\n"
                        : "+f"(acc[mt][n][0]), "+f"(acc[mt][n][1]),
                          "+f"(acc[mt][n][2]), "+f"(acc[mt][n][3])
                        : "r"(ra[mt][0]), "r"(ra[mt][1]), "r"(ra[mt][2]), "r"(ra[mt][3]),
                          "r"(rb[n][0]), "r"(rb[n][1]));
                }
        }
        __syncthreads();
    }
#undef PREFETCH

    // epilogue
#pragma unroll
    for (int mt = 0; mt < 2; mt++) {
        int r0 = bm + wm * 32 + mt * 16 + g;
        int r1 = r0 + 8;
        float bv0 = (r0 < Mstore) ? bias[r0] : 0.f;
        float bv1 = (r1 < Mstore) ? bias[r1] : 0.f;
#pragma unroll
        for (int n = 0; n < NT; n++) {
            long cc = bl + wn * (NT * 8) + n * 8 + tg * 2;
            if (r0 < Mstore) {
                float vx = acc[mt][n][0] + bv0;
                float vy = acc[mt][n][1] + bv0;
                if (MODE == 2) {
                    float2 v; v.x = __expf(vx); v.y = __expf(vy);
                    *(float2*)&Cf[(long)r0 * L + cc] = v;
                } else {
                    if (MODE == 1) { vx = fmaxf(vx, 0.f); vy = fmaxf(vy, 0.f); }
                    *(__half2*)&Ch[(long)r0 * L + cc] = __floats2half2_rn(vx, vy);
                }
            }
            if (r1 < Mstore) {
                float vx = acc[mt][n][2] + bv1;
                float vy = acc[mt][n][3] + bv1;
                if (MODE == 2) {
                    float2 v; v.x = __expf(vx); v.y = __expf(vy);
                    *(float2*)&Cf[(long)r1 * L + cc] = v;
                } else {
                    if (MODE == 1) { vx = fmaxf(vx, 0.f); vy = fmaxf(vy, 0.f); }
                    *(__half2*)&Ch[(long)r1 * L + cc] = __floats2half2_rn(vx, vy);
                }
            }
        }
    }
}

// -------- dustbin: E[64, l] = exp(db2 + dw2 . hidden_d[:, l]) --------
__global__ void dustbin_k(const float* __restrict__ dw2, const float* __restrict__ db2,
                          int L, long zoff) {
    __shared__ float w[128];
    int tid = threadIdx.x;
    if (tid < 128) w[tid] = dw2[tid];
    __syncthreads();
    long l = (long)blockIdx.x * 256 + tid;
    const __half* h = g_hidden + (long)1024 * L + l;
    float acc = db2[0];
#pragma unroll 8
    for (int k = 0; k < 128; k++) acc += w[k] * __half2float(h[(long)k * L]);
    g_Z[zoff + (long)64 * L + l] = __expf(acc);
}

// -------- Sinkhorn both scales (32 blocks), exp space, float4 --------
__global__ void __launch_bounds__(1024) sinkhorn2_k() {
    int blk = blockIdx.x;
    int s = blk >> 4, b = blk & 15;
    int N = s ? N1_ : N0_;
    int L = s ? L1 : L0;
    long zb = (s ? (long)65 * L0 : 0L) + (long)b * N;
    long cb = (s ? (long)B_ * N0_ : 0L) + (long)b * N;

    __shared__ float4 c4[1024];
    __shared__ float r[72];
    int tid = threadIdx.x, lane = tid & 31, warp = tid >> 5;
    float mu = 1.0f / 65.0f;
    float nu = 1.0f / (float)N;
    int n4 = N / 4;

    for (int i = tid; i < n4; i += 1024) c4[i] = make_float4(1.f, 1.f, 1.f, 1.f);
    __syncthreads();

    for (int it = 0; it < 3; it++) {
        for (int k = warp; k < 65; k += 32) {
            const float4* er = (const float4*)(g_Z + (long)k * L + zb);
            float sm = 0.f;
            for (int i = lane; i < n4; i += 32) {
                float4 e = er[i], cc = c4[i];
                sm += e.x * cc.x + e.y * cc.y + e.z * cc.z + e.w * cc.w;
            }
#pragma unroll
            for (int off = 16; off; off >>= 1) sm += __shfl_xor_sync(0xffffffffu, sm, off);
            if (lane == 0) r[k] = mu / sm;
        }
        __syncthreads();
        for (int i = tid; i < n4; i += 1024) {
            const float4* base = (const float4*)(g_Z + zb) + i;
            float4 a = make_float4(0.f, 0.f, 0.f, 0.f);
            int l4 = L / 4;
#pragma unroll 5
            for (int k = 0; k < 65; k++) {
                float4 e = base[(long)k * l4];
                float rk = r[k];
                a.x += e.x * rk; a.y += e.y * rk; a.z += e.z * rk; a.w += e.w * rk;
            }
            c4[i] = make_float4(nu / a.x, nu / a.y, nu / a.z, nu / a.w);
        }
        __syncthreads();
    }
    float4* co = (float4*)(g_c + cb);
    for (int i = tid; i < n4; i += 1024) co[i] = c4[i];
}

// -------- einsum: out[b,c,k] += sum_n feat[c,n] * E[k,n] * c_n --------
__global__ void __launch_bounds__(256)
einsum_k(int obase, int N, int L, long foff, long zoff, long cboff) {
    int b = blockIdx.x;
    int nc0 = blockIdx.y * 128;
    __shared__ float Fs[32][132];
    __shared__ float Ps[32][68];
    int tid = threadIdx.x, tx = tid & 15, ty = tid >> 4;
    long base = (long)b * N;

    float acc[8][4];
#pragma unroll
    for (int i = 0; i < 8; i++)
#pragma unroll
        for (int j = 0; j < 4; j++) acc[i][j] = 0.f;

    for (int nc = nc0; nc < nc0 + 128; nc += 32) {
#pragma unroll
        for (int i = 0; i < 16; i++) {
            int e = tid + i * 256;
            int cch = e >> 5, n = e & 31;
            Fs[n][cch] = __half2float(g_feath[foff + (long)cch * L + base + nc + n]);
        }
        {
            int n = tid & 31;
            float cv = g_c[cboff + base + nc + n];
#pragma unroll
            for (int i = 0; i < 8; i++) {
                int e = tid + i * 256;
                int k = e >> 5;
                Ps[n][k] = g_Z[zoff + (long)k * L + base + nc + n] * cv;
            }
        }
        __syncthreads();
#pragma unroll
        for (int kk = 0; kk < 32; kk++) {
            float a[8], bb[4];
            float4 t;
            t = *(const float4*)&Fs[kk][ty * 4];      a[0]=t.x; a[1]=t.y; a[2]=t.z; a[3]=t.w;
            t = *(const float4*)&Fs[kk][ty * 4 + 64]; a[4]=t.x; a[5]=t.y; a[6]=t.z; a[7]=t.w;
            t = *(const float4*)&Ps[kk][tx * 4];      bb[0]=t.x; bb[1]=t.y; bb[2]=t.z; bb[3]=t.w;
#pragma unroll
            for (int i = 0; i < 8; i++)
#pragma unroll
                for (int j = 0; j < 4; j++) acc[i][j] += a[i] * bb[j];
        }
        __syncthreads();
    }

    float* outp = g_out + ((long)(obase + b)) * (CDIM_ * KK_);
#pragma unroll
    for (int i = 0; i < 8; i++) {
        int rr = (i < 4) ? (ty * 4 + i) : (64 + ty * 4 + i - 4);
#pragma unroll
        for (int j = 0; j < 4; j++)
            atomicAdd(&outp[rr * 64 + tx * 4 + j], acc[i][j]);
    }
}

// -------- final normalization --------
__global__ void __launch_bounds__(256) final_k(float* __restrict__ out) {
    int b = blockIdx.x, tid = threadIdx.x;
    __shared__ float d[8192];
    __shared__ float cn[2][64];
    __shared__ float red[9];
    if (tid < 128) cn[tid >> 6][tid & 63] = 0.f;
    __syncthreads();
    const float* o0 = g_out + (long)b * 8192;
    const float* o1 = g_out + (long)(B_ + b) * 8192;
    for (int e = tid; e < 8192; e += 256) {
        float v0 = o0[e], v1 = o1[e];
        atomicAdd(&cn[0][e & 63], v0 * v0);
        atomicAdd(&cn[1][e & 63], v1 * v1);
    }
    __syncthreads();
    if (tid < 128) {
        float nn = sqrtf(cn[tid >> 6][tid & 63]);
        cn[tid >> 6][tid & 63] = 1.f / fmaxf(nn, 1e-12f);
    }
    __syncthreads();
    float ss = 0.f;
    for (int e = tid; e < 8192; e += 256) {
        int k = e & 63;
        float dv = 0.5f * (o0[e] * cn[0][k] + o1[e] * cn[1][k]);
        d[e] = dv;
        ss += dv * dv;
    }
#pragma unroll
    for (int off = 16; off; off >>= 1) ss += __shfl_xor_sync(0xffffffffu, ss, off);
    if ((tid & 31) == 0) red[tid >> 5] = ss;
    __syncthreads();
    if (tid == 0) {
        float t = 0.f;
        for (int i = 0; i < 8; i++) t += red[i];
        red[8] = 1.f / fmaxf(sqrtf(t), 1e-12f);
    }
    __syncthreads();
    float inv = red[8];
    for (int e = tid; e < 8192; e += 256) out[(long)b * 8192 + e] = d[e] * inv;
}

extern "C" void kernel_launch(void* const* d_in, const int* in_sizes, int n_in,
                              void* d_out, int out_size) {
    (void)in_sizes; (void)n_in; (void)out_size;
    const float* x = (const float*)d_in[0];

    for (int s = 0; s < 2; s++) {
        int base = 1 + s * 12;
        prep_k<<<1728, 256>>>(s,
            (const float*)d_in[base + 0], (const float*)d_in[base + 1],
            (const float*)d_in[base + 4], (const float*)d_in[base + 5],
            (const float*)d_in[base + 8], (const float*)d_in[base + 9],
            (const float*)d_in[base + 2], (const float*)d_in[base + 6]);
    }
    tpose_pool_k<<<(CIN * L1) / 256, 256>>>(x);
    zero_k<<<1024, 256>>>();

    for (int s = 0; s < 2; s++) {
        int base = 1 + s * 12;
        const float* fb2 = (const float*)d_in[base + 3];
        const float* sb2 = (const float*)d_in[base + 7];
        const float* dw2 = (const float*)d_in[base + 10];
        const float* db2 = (const float*)d_in[base + 11];

        int L = s ? L1 : L0;
        int xid = s ? 1 : 0;
        long ws = (long)s * WSTRIDE;
        long foff = s ? (long)CDIM_ * L0 : 0L;
        long zoff = s ? (long)65 * L0 : 0L;

        // fused layer-1 (relu + fp16 store): M=1152
        hgemm<1, 4><<<dim3(9, L / 128), 256>>>(ws, nullptr, (long)s * 1152,
                                               xid, 0L, 0L, CIN, L, 1152);
        // layer-2 feat (bias + fp16 store): M=128
        hgemm<0, 4><<<dim3(1, L / 128), 256>>>(ws + W1SZ, fb2, 0L,
                                               2, 0L, foff, 512, L, 128);
        // layer-2 score (exp + fp32 store -> E): true M=64 tiles
        hgemm<2, 2><<<dim3(1, L / 128), 256>>>(ws + W1SZ + W2FSZ, sb2, 0L,
                                               2, (long)512 * L, zoff, 512, L, 64);
        dustbin_k<<<L / 256, 256>>>(dw2, db2, L, zoff);
    }

    // both scales' Sinkhorn concurrently (32 blocks)
    sinkhorn2_k<<<32, 1024>>>();

    einsum_k<<<dim3(B_, N0_ / 128), 256>>>(0, N0_, L0, 0L, 0L, 0L);
    einsum_k<<<dim3(B_, N1_ / 128), 256>>>(B_, N1_, L1,
                                           (long)CDIM_ * L0, (long)65 * L0,
                                           (long)B_ * N0_);

    final_k<<<B_, 256>>>((float*)d_out);
}